// round 4
// baseline (speedup 1.0000x reference)
#include <cuda_runtime.h>
#include <cuda_bf16.h>

// ---------------------------------------------------------------------------
// SCNLinkPredictor fused pipeline, fp32 baseline with packed f32x2 FFMA.
//
// Inputs (metadata order):
//  0 x        [100000,256] f32      1 neighbors [100000,64] i32
//  2 tar_ei   [2,E] i32             3 beta [1] f32
//  4 cn_w1 [1,256]   5 cn_b1 [256]  6 cn_w2 [256,256]  7 cn_b2 [256]
//  8 cn_w3 [256,256] 9 cn_b3 [256]
// 10 ij_w1 [256,256] 11 ij_b1      12 ij_w2 [256,256] 13 ij_b2
// 14 lin_w1 [256,256] 15 lin_b1    16 lin_w2 [256,1]  17 lin_b2 [1]
// Output: [E,1] f32
//
// Pipeline (4 kernels, sequential on default stream):
//  k0: clear presence flags
//  k1: per-edge CN pairwise-match count (warp/edge, shuffle all-pairs)
//  k2: CN-MLP table for each *occurring* count value (flag-gated blocks)
//  k3: fused main kernel: P=xi*xj -> GEMM1(relu) -> GEMM2(+beta*table[cnt])
//      -> GEMM3(relu) -> dot with lin_w2 -> out
// ---------------------------------------------------------------------------

#define MAXE      131072
#define HD        256
#define NCOUNT    4097          // counts in [0, 64*64]
#define BE        64            // edges per block in main kernel
#define SMEM_MAIN (2 * BE * HD * 4)

__device__ int g_counts[MAXE];
__device__ int g_flags[NCOUNT];
__device__ __align__(16) float g_table[NCOUNT * HD];

// ---------------- packed f32x2 helpers ----------------
__device__ __forceinline__ unsigned long long pack2(float lo, float hi) {
    unsigned long long r;
    asm("mov.b64 %0, {%1, %2};" : "=l"(r) : "f"(lo), "f"(hi));
    return r;
}
__device__ __forceinline__ void unpack2(unsigned long long v, float& lo, float& hi) {
    asm("mov.b64 {%0, %1}, %2;" : "=f"(lo), "=f"(hi) : "l"(v));
}
__device__ __forceinline__ void ffma2(unsigned long long& d,
                                      unsigned long long a, unsigned long long b) {
    asm("fma.rn.f32x2 %0, %1, %2, %0;" : "+l"(d) : "l"(a), "l"(b));
}

// ---------------- k0: clear flags ----------------
__global__ void clear_flags_kernel() {
    int i = blockIdx.x * blockDim.x + threadIdx.x;
    if (i < NCOUNT) g_flags[i] = 0;
}

// ---------------- k1: CN counts (warp per edge) ----------------
__global__ void cn_count_kernel(const int* __restrict__ nbr,
                                const int* __restrict__ tar, int E) {
    int w    = (blockIdx.x * blockDim.x + threadIdx.x) >> 5;
    int lane = threadIdx.x & 31;
    if (w >= E) return;
    int s = tar[w];
    int d = tar[E + w];
    int2 a = ((const int2*)(nbr + (size_t)s * 64))[lane];
    int2 b = ((const int2*)(nbr + (size_t)d * 64))[lane];
    int cnt = 0;
#pragma unroll
    for (int j = 0; j < 32; j++) {
        int v0 = __shfl_sync(0xffffffffu, b.x, j);
        int v1 = __shfl_sync(0xffffffffu, b.y, j);
        cnt += (a.x == v0) + (a.y == v0) + (a.x == v1) + (a.y == v1);
    }
#pragma unroll
    for (int off = 16; off; off >>= 1)
        cnt += __shfl_xor_sync(0xffffffffu, cnt, off);
    if (lane == 0) {
        g_counts[w] = cnt;
        g_flags[cnt] = 1;   // benign write race (same value)
    }
}

// ---------------- k2: CN MLP table for occurring counts ----------------
__global__ void cn_table_kernel(const float* __restrict__ w1, const float* __restrict__ b1,
                                const float* __restrict__ w2, const float* __restrict__ b2,
                                const float* __restrict__ w3, const float* __restrict__ b3) {
    int c = blockIdx.x;
    if (!g_flags[c]) return;
    int h = threadIdx.x;
    __shared__ float sh[HD];
    float cf = (float)c;
    sh[h] = fmaxf(fmaf(cf, w1[h], b1[h]), 0.f);
    __syncthreads();
    float s = b2[h];
#pragma unroll 8
    for (int k = 0; k < HD; k++) s = fmaf(sh[k], w2[k * HD + h], s);
    s = fmaxf(s, 0.f);
    __syncthreads();
    sh[h] = s;
    __syncthreads();
    float t = b3[h];
#pragma unroll 8
    for (int k = 0; k < HD; k++) t = fmaf(sh[k], w3[k * HD + h], t);
    g_table[c * HD + h] = t;
}

// ---------------- main kernel GEMM helpers ----------------
// Thread tile: 8 rows x 8 cols (4 f32x2 pairs). 256 threads:
//   rg = tid>>5 (warp id, 8 row-groups), cg = tid&31 (32 col-groups).
// Cols per thread: {2cg, 2cg+1} + 64*j, j=0..3  (conflict-free LDS/LDG.64).
// A reads are warp-uniform addresses -> broadcast, conflict-free.

__device__ __forceinline__ void load_bgrp(unsigned long long (&bb)[4][4],
                                          const unsigned long long* __restrict__ W8,
                                          int k, int cb) {
#pragma unroll
    for (int kk = 0; kk < 4; kk++)
#pragma unroll
        for (int j = 0; j < 4; j++)
            bb[kk][j] = W8[(k + kk) * 128 + cb + 32 * j];
}

__device__ __forceinline__ void comp_bgrp(unsigned long long (&acc)[8][4],
                                          const unsigned long long (&bb)[4][4],
                                          const float* __restrict__ Ar, int k) {
#pragma unroll
    for (int kk = 0; kk < 4; kk++) {
#pragma unroll
        for (int i = 0; i < 8; i++) {
            float av = Ar[i * HD + k + kk];
            unsigned long long aa = pack2(av, av);
#pragma unroll
            for (int j = 0; j < 4; j++) ffma2(acc[i][j], aa, bb[kk][j]);
        }
    }
}

// MODE 0: out = relu(acc + bias); MODE 1: out = acc + bias + beta*table[cnt]
template <int MODE>
__device__ __forceinline__ void gemm_tile(const float* __restrict__ As,
                                          const float* __restrict__ Wg,
                                          const float* __restrict__ bias,
                                          float* __restrict__ Cs,
                                          float beta, const int* tblrow) {
    int tx = threadIdx.x;
    int cg = tx & 31;
    int rg = tx >> 5;
    const float* Ar = As + rg * 8 * HD;
    const unsigned long long* W8 = (const unsigned long long*)Wg;
    int cb = cg;

    unsigned long long acc[8][4];
#pragma unroll
    for (int i = 0; i < 8; i++)
#pragma unroll
        for (int j = 0; j < 4; j++) acc[i][j] = 0ull;  // bit pattern of (0.f,0.f)

    unsigned long long bb0[4][4], bb1[4][4];
    load_bgrp(bb0, W8, 0, cb);
    for (int k = 0; k < HD; k += 8) {
        load_bgrp(bb1, W8, k + 4, cb);
        comp_bgrp(acc, bb0, Ar, k);
        if (k + 8 < HD) load_bgrp(bb0, W8, k + 8, cb);
        comp_bgrp(acc, bb1, Ar, k + 4);
    }

    // epilogue
    float2 bv[4];
#pragma unroll
    for (int j = 0; j < 4; j++)
        bv[j] = *(const float2*)(bias + 2 * cg + 64 * j);

#pragma unroll
    for (int i = 0; i < 8; i++) {
        int r = rg * 8 + i;
#pragma unroll
        for (int j = 0; j < 4; j++) {
            int c0 = 2 * cg + 64 * j;
            float lo, hi;
            unpack2(acc[i][j], lo, hi);
            lo += bv[j].x;
            hi += bv[j].y;
            if (MODE == 1) {
                float2 tv = *(const float2*)(g_table + tblrow[r] + c0);
                lo = fmaf(beta, tv.x, lo);
                hi = fmaf(beta, tv.y, hi);
            } else {
                lo = fmaxf(lo, 0.f);
                hi = fmaxf(hi, 0.f);
            }
            *(float2*)(Cs + r * HD + c0) = make_float2(lo, hi);
        }
    }
}

// ---------------- k3: fused main kernel ----------------
__global__ void __launch_bounds__(256)
scn_main_kernel(const float* __restrict__ x, const int* __restrict__ tar,
                const float* __restrict__ beta_p,
                const float* __restrict__ ijw1, const float* __restrict__ ijb1,
                const float* __restrict__ ijw2, const float* __restrict__ ijb2,
                const float* __restrict__ lw1, const float* __restrict__ lb1,
                const float* __restrict__ lw2, const float* __restrict__ lb2,
                float* __restrict__ out, int E) {
    extern __shared__ float smem[];
    float* bufA = smem;             // [BE][256]
    float* bufB = smem + BE * HD;   // [BE][256]
    __shared__ int s_src[BE], s_dst[BE], s_tbl[BE];

    int tx = threadIdx.x;
    int e0 = blockIdx.x * BE;

    if (tx < BE) {
        int e = e0 + tx;
        if (e >= E) e = E - 1;
        s_src[tx] = tar[e];
        s_dst[tx] = tar[E + e];
        s_tbl[tx] = g_counts[e] * HD;
    }
    float beta = *beta_p;
    __syncthreads();

    // phase 0: P = xi * xj  -> bufA
    {
        float4* P4 = (float4*)bufA;
        for (int i = tx; i < BE * 64; i += 256) {
            int r = i >> 6, c = i & 63;
            const float4* xa = (const float4*)(x + (size_t)s_src[r] * HD);
            const float4* xb = (const float4*)(x + (size_t)s_dst[r] * HD);
            float4 a = xa[c], b = xb[c];
            P4[i] = make_float4(a.x * b.x, a.y * b.y, a.z * b.z, a.w * b.w);
        }
    }
    __syncthreads();

    // GEMM1: g = relu(P @ ij_w1 + ij_b1)            bufA -> bufB
    gemm_tile<0>(bufA, ijw1, ijb1, bufB, 0.f, s_tbl);
    __syncthreads();
    // GEMM2: pre = g @ ij_w2 + ij_b2 + beta*table   bufB -> bufA
    gemm_tile<1>(bufB, ijw2, ijb2, bufA, beta, s_tbl);
    __syncthreads();
    // GEMM3: z = relu(pre @ lin_w1 + lin_b1)        bufA -> bufB
    gemm_tile<0>(bufA, lw1, lb1, bufB, 0.f, s_tbl);
    __syncthreads();

    // final: out[e] = z . lin_w2 + lin_b2   (warp handles 8 rows)
    {
        int lane = tx & 31, w = tx >> 5;
        float wreg[8];
#pragma unroll
        for (int t = 0; t < 8; t++) wreg[t] = lw2[lane + 32 * t];
        float lb2v = *lb2;
#pragma unroll
        for (int rr = 0; rr < 8; rr++) {
            int r = w * 8 + rr;
            float s = 0.f;
#pragma unroll
            for (int t = 0; t < 8; t++)
                s = fmaf(bufB[r * HD + lane + 32 * t], wreg[t], s);
#pragma unroll
            for (int off = 16; off; off >>= 1)
                s += __shfl_xor_sync(0xffffffffu, s, off);
            if (lane == 0 && e0 + r < E) out[e0 + r] = s + lb2v;
        }
    }
}

// ---------------------------------------------------------------------------
extern "C" void kernel_launch(void* const* d_in, const int* in_sizes, int n_in,
                              void* d_out, int out_size) {
    const float* x    = (const float*)d_in[0];
    const int*   nbr  = (const int*)d_in[1];
    const int*   tar  = (const int*)d_in[2];
    const float* beta = (const float*)d_in[3];
    const float* cw1  = (const float*)d_in[4];
    const float* cb1  = (const float*)d_in[5];
    const float* cw2  = (const float*)d_in[6];
    const float* cb2  = (const float*)d_in[7];
    const float* cw3  = (const float*)d_in[8];
    const float* cb3  = (const float*)d_in[9];
    const float* ijw1 = (const float*)d_in[10];
    const float* ijb1 = (const float*)d_in[11];
    const float* ijw2 = (const float*)d_in[12];
    const float* ijb2 = (const float*)d_in[13];
    const float* lw1  = (const float*)d_in[14];
    const float* lb1  = (const float*)d_in[15];
    const float* lw2  = (const float*)d_in[16];
    const float* lb2  = (const float*)d_in[17];
    float* out = (float*)d_out;

    int E = in_sizes[2] / 2;
    if (E > MAXE) E = MAXE;

    cudaFuncSetAttribute(scn_main_kernel,
                         cudaFuncAttributeMaxDynamicSharedMemorySize, SMEM_MAIN);

    clear_flags_kernel<<<(NCOUNT + 255) / 256, 256>>>();
    cn_count_kernel<<<(E + 7) / 8, 256>>>(nbr, tar, E);
    cn_table_kernel<<<NCOUNT, 256>>>(cw1, cb1, cw2, cb2, cw3, cb3);
    scn_main_kernel<<<(E + BE - 1) / BE, 256, SMEM_MAIN>>>(
        x, tar, beta, ijw1, ijb1, ijw2, ijb2, lw1, lb1, lw2, lb2, out, E);
}

// round 6
// speedup vs baseline: 1.9200x; 1.9200x over previous
#include <cuda_runtime.h>
#include <cuda_bf16.h>
#include <cstdint>

// ---------------------------------------------------------------------------
// SCNLinkPredictor — mma.sync tf32 pipeline (family-portable PTX only;
// tcgen05 is unavailable because the harness emits plain compute_103 PTX).
//
//  k0 clear flags | k1 CN counts | k2 CN-MLP table | k3 weight tf32-round
//  k4 main: per-CTA 64 edges: P=xi*xj -> SMEM A (fragment-permuted tf32)
//     3x [ mma.sync m16n8k8 tf32 GEMM (M64,N256,K256), W streamed via
//          4-deep cp.async ring -> epilogue(bias/relu/beta*table) -> SMEM A ]
//     final layer folded into fragments: relu(z)+dot(lin_w2) -> out.
// ---------------------------------------------------------------------------

#define MAXE   131072
#define HD     256
#define NCOUNT 4097
#define BE     64

__device__ int g_counts[MAXE];
__device__ int g_flags[NCOUNT];
__device__ __align__(16) float    g_table[NCOUNT * HD];
__device__ __align__(16) uint32_t g_wtf[3 * HD * HD];   // tf32-rounded weights [k][n]

// ---------------- SMEM layout (dynamic) ----------------
#define ACT_OFF   0                     // 64x256 tf32, fragment-permuted, 65536 B
#define WB_OFF    65536                 // 4 ring buffers, 32x(256+8) f32 each
#define WB_STRIDE 33792
#define BIAS_OFF  (WB_OFF + 4 * WB_STRIDE)   // 200704: [b1|b2|lb1|lw2] 1024 f32
#define SMEM_SZ   (BIAS_OFF + 4096)          // 204800

// ---------------- PTX helpers ----------------
__device__ __forceinline__ uint32_t smem_u32(const void* p) {
    uint32_t a;
    asm("{ .reg .u64 t; cvta.to.shared.u64 t, %1; cvt.u32.u64 %0, t; }"
        : "=r"(a) : "l"(p));
    return a;
}
__device__ __forceinline__ uint32_t f2tf(float f) {
    uint32_t r;
    asm("cvt.rna.tf32.f32 %0, %1;" : "=r"(r) : "f"(f));
    return r;
}
__device__ __forceinline__ void mma8(float* c, const uint32_t* a,
                                     uint32_t b0, uint32_t b1) {
    asm volatile(
        "mma.sync.aligned.m16n8k8.row.col.f32.tf32.tf32.f32 "
        "{%0,%1,%2,%3}, {%4,%5,%6,%7}, {%8,%9}, {%0,%1,%2,%3};"
        : "+f"(c[0]), "+f"(c[1]), "+f"(c[2]), "+f"(c[3])
        : "r"(a[0]), "r"(a[1]), "r"(a[2]), "r"(a[3]), "r"(b0), "r"(b1));
}
__device__ __forceinline__ void lds128(uint32_t* v, uint32_t addr) {
    asm volatile("ld.shared.v4.b32 {%0,%1,%2,%3}, [%4];"
                 : "=r"(v[0]), "=r"(v[1]), "=r"(v[2]), "=r"(v[3]) : "r"(addr));
}
__device__ __forceinline__ uint32_t lds32(uint32_t addr) {
    uint32_t v;
    asm volatile("ld.shared.b32 %0, [%1];" : "=r"(v) : "r"(addr));
    return v;
}
__device__ __forceinline__ void sts32(uint32_t addr, uint32_t v) {
    asm volatile("st.shared.b32 [%0], %1;" :: "r"(addr), "r"(v));
}
#define CP_ASYNC16(dst, src) \
    asm volatile("cp.async.cg.shared.global [%0], [%1], 16;" :: "r"(dst), "l"(src))
#define CP_COMMIT() asm volatile("cp.async.commit_group;" ::: "memory")
#define CP_WAIT(n)  asm volatile("cp.async.wait_group %0;" :: "n"(n) : "memory")

// ---------------- k0..k2: CN path (proven) ----------------
__global__ void clear_flags_kernel() {
    int i = blockIdx.x * blockDim.x + threadIdx.x;
    if (i < NCOUNT) g_flags[i] = 0;
}

__global__ void cn_count_kernel(const int* __restrict__ nbr,
                                const int* __restrict__ tar, int E) {
    int w = (blockIdx.x * blockDim.x + threadIdx.x) >> 5;
    int lane = threadIdx.x & 31;
    if (w >= E) return;
    int s = tar[w];
    int d = tar[E + w];
    int2 a = ((const int2*)(nbr + (size_t)s * 64))[lane];
    int2 b = ((const int2*)(nbr + (size_t)d * 64))[lane];
    int cnt = 0;
#pragma unroll
    for (int j = 0; j < 32; j++) {
        int v0 = __shfl_sync(0xffffffffu, b.x, j);
        int v1 = __shfl_sync(0xffffffffu, b.y, j);
        cnt += (a.x == v0) + (a.y == v0) + (a.x == v1) + (a.y == v1);
    }
#pragma unroll
    for (int off = 16; off; off >>= 1)
        cnt += __shfl_xor_sync(0xffffffffu, cnt, off);
    if (lane == 0) { g_counts[w] = cnt; g_flags[cnt] = 1; }
}

__global__ void cn_table_kernel(const float* __restrict__ w1, const float* __restrict__ b1,
                                const float* __restrict__ w2, const float* __restrict__ b2,
                                const float* __restrict__ w3, const float* __restrict__ b3) {
    int c = blockIdx.x;
    if (!g_flags[c]) return;
    int h = threadIdx.x;
    __shared__ float sh[HD];
    float cf = (float)c;
    sh[h] = fmaxf(fmaf(cf, w1[h], b1[h]), 0.f);
    __syncthreads();
    float s = b2[h];
#pragma unroll 8
    for (int k = 0; k < HD; k++) s = fmaf(sh[k], w2[k * HD + h], s);
    s = fmaxf(s, 0.f);
    __syncthreads();
    sh[h] = s;
    __syncthreads();
    float t = b3[h];
#pragma unroll 8
    for (int k = 0; k < HD; k++) t = fmaf(sh[k], w3[k * HD + h], t);
    g_table[c * HD + h] = t;
}

// ---------------- k3: tf32-round the GEMM weights (keep [k][n]) ----------------
__global__ void wprep_kernel(const float* __restrict__ w0,
                             const float* __restrict__ w1,
                             const float* __restrict__ w2) {
    int i = blockIdx.x * blockDim.x + threadIdx.x;
    if (i >= 3 * HD * HD) return;
    const float* w = (i < HD * HD) ? w0 : (i < 2 * HD * HD) ? w1 : w2;
    g_wtf[i] = f2tf(w[i & (HD * HD - 1)]);
}

// ---------------- main kernel ----------------
// A (activations) live in SMEM in a fragment-permuted layout so that each
// thread's m16k8 tf32 A-fragment {a0,a1,a2,a3} is one 16B LDS.128:
//   tile (kstep, mt) at offset ((kstep*4+mt)*512); within tile: lane*16 + v*4
//   lane = (row&7)*4 + (col&3),  v = ((row>>3)&1) | (((col>>2)&1)<<1)
//   (row = m in [0,64), col = k in [0,256), kstep = col>>3, mt = row>>4)

__device__ __forceinline__ void load_wchunk(uint32_t sb, int buf, int t) {
    int tx = threadIdx.x;
    const uint32_t* src = g_wtf + (t >> 3) * (HD * HD) + (t & 7) * 32 * HD;
    uint32_t dst0 = sb + WB_OFF + buf * WB_STRIDE;
#pragma unroll
    for (int it = 0; it < 8; ++it) {
        int qd = it * 256 + tx;             // 2048 16B units
        int row = qd >> 6, c4 = qd & 63;    // row: k in chunk, c4: n/4
        CP_ASYNC16(dst0 + row * 1056 + c4 * 16, src + row * HD + c4 * 4);
    }
    CP_COMMIT();
}

// epilogue: act = f(C + bias [+ beta*table]) stored back in permuted layout
template <int RELU, int TAB>
__device__ __forceinline__ void epilogue(uint32_t sb, float acc[4][4][4],
                                         const float* __restrict__ bias,
                                         const int* __restrict__ s_tbl,
                                         float beta, int w, int lane) {
    int q = lane & 3, gid = lane >> 2;
#pragma unroll
    for (int mt = 0; mt < 4; ++mt) {
        int r0 = 16 * mt + gid;
        int trow0 = 0, trow1 = 0;
        if (TAB) { trow0 = s_tbl[r0]; trow1 = s_tbl[r0 + 8]; }
#pragma unroll
        for (int nt = 0; nt < 4; ++nt) {
            int colb = 32 * w + 8 * nt + 2 * q;
            float2 bv = *(const float2*)(bias + colb);
            float v0 = acc[mt][nt][0] + bv.x;
            float v1 = acc[mt][nt][1] + bv.y;
            float v2 = acc[mt][nt][2] + bv.x;
            float v3 = acc[mt][nt][3] + bv.y;
            if (TAB) {
                float2 t0 = __ldg((const float2*)(g_table + trow0 + colb));
                float2 t1 = __ldg((const float2*)(g_table + trow1 + colb));
                v0 = fmaf(beta, t0.x, v0); v1 = fmaf(beta, t0.y, v1);
                v2 = fmaf(beta, t1.x, v2); v3 = fmaf(beta, t1.y, v3);
            }
            if (RELU) {
                v0 = fmaxf(v0, 0.f); v1 = fmaxf(v1, 0.f);
                v2 = fmaxf(v2, 0.f); v3 = fmaxf(v3, 0.f);
            }
            uint32_t base = sb + ACT_OFF + ((4 * w + nt) * 4 + mt) * 512
                          + gid * 64 + (q & 1) * 32 + (q >> 1) * 8;
            sts32(base + 0,  f2tf(v0));    // (r0, colb)
            sts32(base + 16, f2tf(v1));    // (r0, colb+1)
            sts32(base + 4,  f2tf(v2));    // (r0+8, colb)
            sts32(base + 20, f2tf(v3));    // (r0+8, colb+1)
        }
    }
}

__global__ void __launch_bounds__(256, 1)
scn_mma_kernel(const float* __restrict__ x, const int* __restrict__ tar,
               const float* __restrict__ beta_p,
               const float* __restrict__ ijb1, const float* __restrict__ ijb2,
               const float* __restrict__ lb1,  const float* __restrict__ lw2,
               const float* __restrict__ lb2,  float* __restrict__ out, int E) {
    extern __shared__ char smem[];
    uint32_t sb = smem_u32(smem);
    int tx = threadIdx.x, w = tx >> 5, lane = tx & 31;
    int q = lane & 3, gid = lane >> 2;
    int e0 = blockIdx.x * BE;

    __shared__ int   s_src[BE], s_dst[BE], s_tbl[BE];
    __shared__ float s_red[BE];

    // start streaming the first 3 weight chunks immediately
    load_wchunk(sb, 0, 0);
    load_wchunk(sb, 1, 1);
    load_wchunk(sb, 2, 2);

    float* sbias = (float*)(smem + BIAS_OFF);
    for (int i = tx; i < 1024; i += 256) {
        float v;
        if      (i < 256) v = ijb1[i];
        else if (i < 512) v = ijb2[i - 256];
        else if (i < 768) v = lb1[i - 512];
        else              v = lw2[i - 768];
        sbias[i] = v;
    }
    if (tx < BE) {
        int e = e0 + tx; if (e >= E) e = E - 1;
        s_src[tx] = tar[e];
        s_dst[tx] = tar[E + e];
        s_tbl[tx] = g_counts[e] * HD;
        s_red[tx] = 0.f;
    }
    __syncthreads();

    float beta = *beta_p;
    float lb2v = *lb2;

    // ---- gather: A = tf32(xi * xj), fragment-permuted ----
#pragma unroll
    for (int it = 0; it < 16; ++it) {
        int i = it * 256 + tx;              // 1024 float4 slots
        int m = i >> 6, c4 = i & 63;
        const float4* xa = (const float4*)(x + (size_t)s_src[m] * HD);
        const float4* xb = (const float4*)(x + (size_t)s_dst[m] * HD);
        float4 a = xa[c4], b = xb[c4];
        uint32_t base = sb + ACT_OFF + ((c4 >> 1) * 4 + (m >> 4)) * 512
                      + (m & 7) * 64 + (((m >> 3) & 1) + 2 * (c4 & 1)) * 4;
        sts32(base + 0,  f2tf(a.x * b.x));
        sts32(base + 16, f2tf(a.y * b.y));
        sts32(base + 32, f2tf(a.z * b.z));
        sts32(base + 48, f2tf(a.w * b.w));
    }
    __syncthreads();

    float acc[4][4][4];

#pragma unroll 1
    for (int t = 0; t < 24; ++t) {
        int g = t >> 3, c = t & 7;
        if (c == 0) {
#pragma unroll
            for (int mt = 0; mt < 4; ++mt)
#pragma unroll
                for (int nt = 0; nt < 4; ++nt)
#pragma unroll
                    for (int i = 0; i < 4; ++i) acc[mt][nt][i] = 0.f;
        }
        if (t + 3 < 24) load_wchunk(sb, (t + 3) & 3, t + 3);
        int rem = 23 - t;
        if (rem >= 3)      CP_WAIT(3);
        else if (rem == 2) CP_WAIT(2);
        else if (rem == 1) CP_WAIT(1);
        else               CP_WAIT(0);
        __syncthreads();

        uint32_t wb0 = sb + WB_OFF + (t & 3) * WB_STRIDE
                     + (q * 264 + 32 * w + gid) * 4;
#pragma unroll
        for (int ks = 0; ks < 4; ++ks) {
            int kstep = c * 4 + ks;
            uint32_t a[4][4];
            uint32_t ab = sb + ACT_OFF + kstep * 2048 + lane * 16;
#pragma unroll
            for (int mt = 0; mt < 4; ++mt) lds128(a[mt], ab + mt * 512);
            uint32_t b0[4], b1[4];
            uint32_t wk = wb0 + ks * 8448;          // +8 k-rows per kstep
#pragma unroll
            for (int nt = 0; nt < 4; ++nt) {
                b0[nt] = lds32(wk + nt * 32);
                b1[nt] = lds32(wk + 4224 + nt * 32); // +4 k-rows
            }
#pragma unroll
            for (int mt = 0; mt < 4; ++mt)
#pragma unroll
                for (int nt = 0; nt < 4; ++nt)
                    mma8(acc[mt][nt], a[mt], b0[nt], b1[nt]);
        }
        __syncthreads();

        if (c == 7) {
            if (g == 0) {
                epilogue<1, 0>(sb, acc, sbias,       s_tbl, beta, w, lane);
            } else if (g == 1) {
                epilogue<0, 1>(sb, acc, sbias + 256, s_tbl, beta, w, lane);
            } else {
                // final: out = relu(C + lb1) . lw2 + lb2, folded in fragments
#pragma unroll
                for (int mt = 0; mt < 4; ++mt) {
                    float p0 = 0.f, p1 = 0.f;
#pragma unroll
                    for (int nt = 0; nt < 4; ++nt) {
                        int colb = 32 * w + 8 * nt + 2 * q;
                        float2 lb = *(const float2*)(sbias + 512 + colb);
                        float2 lw = *(const float2*)(sbias + 768 + colb);
                        p0 = fmaf(fmaxf(acc[mt][nt][0] + lb.x, 0.f), lw.x, p0);
                        p0 = fmaf(fmaxf(acc[mt][nt][1] + lb.y, 0.f), lw.y, p0);
                        p1 = fmaf(fmaxf(acc[mt][nt][2] + lb.x, 0.f), lw.x, p1);
                        p1 = fmaf(fmaxf(acc[mt][nt][3] + lb.y, 0.f), lw.y, p1);
                    }
                    p0 += __shfl_xor_sync(0xffffffffu, p0, 1);
                    p0 += __shfl_xor_sync(0xffffffffu, p0, 2);
                    p1 += __shfl_xor_sync(0xffffffffu, p1, 1);
                    p1 += __shfl_xor_sync(0xffffffffu, p1, 2);
                    if (q == 0) {
                        atomicAdd(&s_red[16 * mt + gid],     p0);
                        atomicAdd(&s_red[16 * mt + gid + 8], p1);
                    }
                }
            }
            __syncthreads();
        }
    }

    if (tx < BE && e0 + tx < E) out[e0 + tx] = s_red[tx] + lb2v;
}

// ---------------------------------------------------------------------------
extern "C" void kernel_launch(void* const* d_in, const int* in_sizes, int n_in,
                              void* d_out, int out_size) {
    const float* x    = (const float*)d_in[0];
    const int*   nbr  = (const int*)d_in[1];
    const int*   tar  = (const int*)d_in[2];
    const float* beta = (const float*)d_in[3];
    const float* cw1  = (const float*)d_in[4];
    const float* cb1  = (const float*)d_in[5];
    const float* cw2  = (const float*)d_in[6];
    const float* cb2  = (const float*)d_in[7];
    const float* cw3  = (const float*)d_in[8];
    const float* cb3  = (const float*)d_in[9];
    const float* ijw1 = (const float*)d_in[10];
    const float* ijb1 = (const float*)d_in[11];
    const float* ijw2 = (const float*)d_in[12];
    const float* ijb2 = (const float*)d_in[13];
    const float* lw1  = (const float*)d_in[14];
    const float* lb1  = (const float*)d_in[15];
    const float* lw2  = (const float*)d_in[16];
    const float* lb2  = (const float*)d_in[17];
    float* out = (float*)d_out;

    int E = in_sizes[2] / 2;
    if (E > MAXE) E = MAXE;

    cudaFuncSetAttribute(scn_mma_kernel,
                         cudaFuncAttributeMaxDynamicSharedMemorySize, SMEM_SZ);

    clear_flags_kernel<<<(NCOUNT + 255) / 256, 256>>>();
    wprep_kernel<<<(3 * HD * HD + 255) / 256, 256>>>(ijw1, ijw2, lw1);
    cn_count_kernel<<<(E + 7) / 8, 256>>>(nbr, tar, E);
    cn_table_kernel<<<NCOUNT, 256>>>(cw1, cb1, cw2, cb2, cw3, cb3);
    scn_mma_kernel<<<(E + BE - 1) / BE, 256, SMEM_SZ>>>(
        x, tar, beta, ijb1, ijb2, lb1, lw2, lb2, out, E);
}